// round 9
// baseline (speedup 1.0000x reference)
#include <cuda_runtime.h>
#include <cuda_bf16.h>
#include <math.h>
#include <stdint.h>

#define MROWS  256
#define INF_   768
#define SHORTN 2000
#define NHEAD  2003
#define LTGT   20

// clusters: lows 2000,12000,40000,100000; OSZ 10000,28000,60000; HSZ 384,192,96
// tail x-block bases: cl0 -> 0 (79 blocks), cl1 -> 79 (219), cl2 -> 298 (469); total 767

// ---------------- device scratch ----------------
__device__ __align__(16) __nv_bfloat16 g_xb[MROWS * INF_];
__device__ __align__(16) __nv_bfloat16 g_hb[MROWS * 672];
__device__ __align__(16) float          g_hl[MROWS * NHEAD];
__device__ float g_rowAcc[MROWS];
__device__ float g_num[MROWS];
__device__ float g_active[MROWS * 3];
__device__ float g_root[MROWS * 3];
__device__ int   g_uniq[MROWS * LTGT];
__device__ int   g_tpack[MROWS * LTGT];   // (blk<<14)|(row<<7)|col, or 0x7FFFFFFF

__device__ __forceinline__ uint32_t smem_u32(const void* p) {
    uint32_t a;
    asm("{ .reg .u64 t; cvta.to.shared.u64 t, %1; cvt.u32.u64 %0, t; }" : "=r"(a) : "l"(p));
    return a;
}

#define LDSM_X4(d0, d1, d2, d3, addr) \
    asm volatile("ldmatrix.sync.aligned.m8n8.x4.shared.b16 {%0,%1,%2,%3}, [%4];" \
        : "=r"(d0), "=r"(d1), "=r"(d2), "=r"(d3) : "r"(addr))

#define MMA16816(c, a, b) \
    asm volatile("mma.sync.aligned.m16n8k16.row.col.f32.bf16.bf16.f32 " \
        "{%0,%1,%2,%3},{%4,%5,%6,%7},{%8,%9},{%0,%1,%2,%3};" \
        : "+f"((c)[0]), "+f"((c)[1]), "+f"((c)[2]), "+f"((c)[3]) \
        : "r"((a)[0]), "r"((a)[1]), "r"((a)[2]), "r"((a)[3]), "r"((b)[0]), "r"((b)[1]))

// ---------------- warp-MMA mainloop (K-chunk 64, 128B smem rows) ----------------
__device__ __forceinline__ void mma_loop(
    const __nv_bfloat16* __restrict__ A, int ldA, int bm0,
    const float* __restrict__ W, int nloc, int nval, int K,
    __nv_bfloat16* smA, __nv_bfloat16* smB, float c[2][8][4])
{
    int tid = threadIdx.x;
    int lane = tid & 31, wid = tid >> 5;
    int wm = wid & 3, wn = wid >> 2;
    int lo3 = lane & 7, gg1 = (lane >> 3) & 1, gg2 = (lane >> 4) & 1;
    uint32_t smAu = smem_u32(smA), smBu = smem_u32(smB);

    int nchunk = (K + 63) >> 6;
    for (int ch = 0; ch < nchunk; ++ch) {
        int kbase = ch << 6;
        int kreal = K - kbase; if (kreal > 64) kreal = 64;
        __syncthreads();

        #pragma unroll
        for (int it = 0; it < 4; ++it) {
            int idx = tid + it * 256;
            int r = idx >> 3, kc = idx & 7;
            if (kc * 8 < kreal) {
                uint4 v = *reinterpret_cast<const uint4*>(
                    A + (size_t)(bm0 + r) * ldA + kbase + kc * 8);
                *reinterpret_cast<uint4*>(
                    reinterpret_cast<char*>(smA) + r * 128 + ((kc ^ (r & 7)) << 4)) = v;
            }
        }
        #pragma unroll
        for (int it = 0; it < 4; ++it) {
            int idx = tid + it * 256;
            int r = idx >> 3, kc = idx & 7;
            if (kc * 8 < kreal) {
                uint4 o = make_uint4(0u, 0u, 0u, 0u);
                if (r < nval) {
                    const float* s = W + (size_t)(nloc + r) * K + kbase + kc * 8;
                    float4 v0 = *reinterpret_cast<const float4*>(s);
                    float4 v1 = *reinterpret_cast<const float4*>(s + 4);
                    asm("cvt.rn.bf16x2.f32 %0, %1, %2;" : "=r"(o.x) : "f"(v0.y), "f"(v0.x));
                    asm("cvt.rn.bf16x2.f32 %0, %1, %2;" : "=r"(o.y) : "f"(v0.w), "f"(v0.z));
                    asm("cvt.rn.bf16x2.f32 %0, %1, %2;" : "=r"(o.z) : "f"(v1.y), "f"(v1.x));
                    asm("cvt.rn.bf16x2.f32 %0, %1, %2;" : "=r"(o.w) : "f"(v1.w), "f"(v1.z));
                }
                *reinterpret_cast<uint4*>(
                    reinterpret_cast<char*>(smB) + r * 128 + ((kc ^ (r & 7)) << 4)) = o;
            }
        }
        __syncthreads();

        int ks = kreal >> 4;
        for (int s = 0; s < ks; ++s) {
            uint32_t a[2][4];
            #pragma unroll
            for (int t = 0; t < 2; ++t) {
                int row = wm * 32 + t * 16 + gg1 * 8 + lo3;
                uint32_t ad = smAu + row * 128 + (((2 * s + gg2) ^ (row & 7)) << 4);
                LDSM_X4(a[t][0], a[t][1], a[t][2], a[t][3], ad);
            }
            uint32_t b[8][2];
            #pragma unroll
            for (int p = 0; p < 4; ++p) {
                int row = wn * 64 + p * 16 + gg2 * 8 + lo3;
                uint32_t bd = smBu + row * 128 + (((2 * s + gg1) ^ (row & 7)) << 4);
                LDSM_X4(b[2 * p][0], b[2 * p][1], b[2 * p + 1][0], b[2 * p + 1][1], bd);
            }
            #pragma unroll
            for (int t = 0; t < 2; ++t)
                #pragma unroll
                for (int n = 0; n < 8; ++n)
                    MMA16816(c[t][n], a[t], b[n]);
        }
    }
    __syncthreads();
}

// ---------------- prep: x -> bf16, per-row init, target packing ----------------
__global__ void prep_kernel(const float* __restrict__ x, const int* __restrict__ tgt) {
    int b = blockIdx.x;
    int tid = threadIdx.x;
    for (int k = tid; k < INF_; k += 256)
        g_xb[b * INF_ + k] = __float2bfloat16(x[(size_t)b * INF_ + k]);

    if (tid < 32) {
        int lane = tid;
        int t = (lane < LTGT) ? tgt[b * LTGT + lane] : -1;
        int uniq = (lane < LTGT) ? 1 : 0;
        #pragma unroll
        for (int j = 0; j < LTGT; ++j) {
            int tj = __shfl_sync(0xffffffffu, t, j);
            if (j < lane && tj == t) uniq = 0;
        }
        if (lane < LTGT) {
            g_uniq[b * LTGT + lane] = uniq;
            int pk = 0x7FFFFFFF;
            if (uniq && t >= SHORTN) {
                int xb, col;
                if (t < 12000)      { col = t - 2000;  xb = 0   + (col >> 7); }
                else if (t < 40000) { col = t - 12000; xb = 79  + (col >> 7); }
                else                { col = t - 40000; xb = 298 + (col >> 7); }
                int key = (b >> 7) * 767 + xb;
                pk = (key << 14) | ((b & 127) << 7) | (col & 127);
            }
            g_tpack[b * LTGT + lane] = pk;
        }

        const int lows[4] = {2000, 12000, 40000, 100000};
        float num = (float)SHORTN;
        #pragma unroll
        for (int i = 0; i < 3; ++i) {
            bool in = (lane < LTGT) && (t >= lows[i]) && (t < lows[i + 1]);
            unsigned ball = __ballot_sync(0xffffffffu, in);
            float a = ball ? 1.f : 0.f;
            if (lane == 0) g_active[b * 3 + i] = a;
            num += (1.f - a) + a * (float)(lows[i + 1] - lows[i]);
        }
        if (lane == 0) { g_num[b] = num; g_rowAcc[b] = 0.f; }
    }
}

// ---------------- mm1: head + hidden GEMMs (128x128) ----------------
__global__ void __launch_bounds__(256) mm1_kernel(const float* __restrict__ headW,
                                                  const float* __restrict__ w1_0,
                                                  const float* __restrict__ w1_1,
                                                  const float* __restrict__ w1_2) {
    __shared__ __align__(16) __nv_bfloat16 smA[128 * 64];
    __shared__ __align__(16) __nv_bfloat16 smB[128 * 64];

    int t = blockIdx.x;
    int bm0 = blockIdx.y * 128;
    const float* W; int ldc, nloc, nval, mode, hoff;
    if (t < 16)      { W = headW; ldc = NHEAD; nloc = t << 7;        nval = NHEAD - nloc; if (nval > 128) nval = 128; mode = 1; hoff = 0; }
    else if (t < 19) { W = w1_0;  ldc = 384;   nloc = (t - 16) << 7; nval = 128; mode = 0; hoff = 0; }
    else if (t < 21) { W = w1_1;  ldc = 192;   nloc = (t - 19) << 7; nval = 192 - nloc; if (nval > 128) nval = 128; mode = 0; hoff = 98304; }
    else             { W = w1_2;  ldc = 96;    nloc = 0;             nval = 96;  mode = 0; hoff = 147456; }

    float c[2][8][4] = {};
    mma_loop(g_xb, INF_, bm0, W, nloc, nval, INF_, smA, smB, c);

    int tid = threadIdx.x;
    int lane = tid & 31, wid = tid >> 5;
    int wm = wid & 3, wn = wid >> 2;
    float* sRow = reinterpret_cast<float*>(smA);
    if (mode == 1) { if (tid < 128) sRow[tid] = 0.f; }
    __syncthreads();

    float rs[2][2] = {{0.f, 0.f}, {0.f, 0.f}};
    #pragma unroll
    for (int tt = 0; tt < 2; ++tt) {
        int r0 = bm0 + wm * 32 + tt * 16 + (lane >> 2);
        #pragma unroll
        for (int n = 0; n < 8; ++n) {
            int col = wn * 64 + n * 8 + (lane & 3) * 2;
            #pragma unroll
            for (int q = 0; q < 2; ++q) {
                if (col + q < nval) {
                    float l0 = c[tt][n][q];
                    float l1 = c[tt][n][2 + q];
                    if (mode == 1) {
                        g_hl[(size_t)r0 * ldc + nloc + col + q] = l0;
                        g_hl[(size_t)(r0 + 8) * ldc + nloc + col + q] = l1;
                        rs[tt][0] += fmaxf(l0, 0.f) + log1pf(__expf(-fabsf(l0)));
                        rs[tt][1] += fmaxf(l1, 0.f) + log1pf(__expf(-fabsf(l1)));
                    } else {
                        // hidden pre-LN logits staged as fp32 in g_hl? No: store raw to bf16 later.
                        // store fp32 hidden into g_hl scratch region is not needed; write to hb after LN.
                        // Here we store pre-LN values into g_hb temporarily as fp32 is impossible;
                        // instead stash into g_hl tail region (unused) — but simpler: reuse g_hl? No.
                        // Store to a dedicated fp32 staging: reuse g_hl is unsafe (head uses all).
                        // We keep a small fp32 staging buffer below.
                        extern __device__ float g_hstage[];
                        g_hstage[hoff + (size_t)r0 * ldc + nloc + col + q] = l0;
                        g_hstage[hoff + (size_t)(r0 + 8) * ldc + nloc + col + q] = l1;
                    }
                }
            }
        }
    }
    if (mode == 1) {
        #pragma unroll
        for (int tt = 0; tt < 2; ++tt) {
            int lr = wm * 32 + tt * 16 + (lane >> 2);
            atomicAdd(&sRow[lr], rs[tt][0]);
            atomicAdd(&sRow[lr + 8], rs[tt][1]);
        }
        __syncthreads();
        if (tid < 128) atomicAdd(&g_rowAcc[bm0 + tid], sRow[tid]);
    }
}

__device__ __align__(16) float g_hstage[MROWS * 672];

// ---------------- LayerNorm + ReLU -> bf16 ----------------
__global__ void ln_kernel(const float* __restrict__ p1a, const float* __restrict__ p2a,
                          const float* __restrict__ p1b, const float* __restrict__ p2b,
                          const float* __restrict__ p1c, const float* __restrict__ p2c) {
    int ci = blockIdx.y;
    int b = blockIdx.x;
    int H, hoff; const float* p1; const float* p2;
    if (ci == 0)      { H = 384; hoff = 0;      p1 = p1a; p2 = p2a; }
    else if (ci == 1) { H = 192; hoff = 98304;  p1 = p1b; p2 = p2b; }
    else              { H = 96;  hoff = 147456; p1 = p1c; p2 = p2c; }
    const float* row = g_hstage + hoff + (size_t)b * H;
    __nv_bfloat16* rowb = g_hb + hoff + (size_t)b * H;

    float v1 = p1[0], v2 = p2[0];
    const float* gp = (fabsf(v1 - 1.f) <= fabsf(v2 - 1.f)) ? p1 : p2;
    const float* bp = (gp == p1) ? p2 : p1;

    int tid = threadIdx.x;   // 128
    float s = 0.f, ss = 0.f;
    for (int k = tid; k < H; k += 128) {
        float v = row[k];
        s += v; ss += v * v;
    }
    #pragma unroll
    for (int o = 16; o; o >>= 1) {
        s  += __shfl_xor_sync(0xffffffffu, s, o);
        ss += __shfl_xor_sync(0xffffffffu, ss, o);
    }
    __shared__ float sh[10];
    int w = tid >> 5;
    if ((tid & 31) == 0) { sh[w] = s; sh[4 + w] = ss; }
    __syncthreads();
    if (tid == 0) {
        float S = sh[0] + sh[1] + sh[2] + sh[3];
        float SS = sh[4] + sh[5] + sh[6] + sh[7];
        sh[8] = S / (float)H;
        sh[9] = SS / (float)H;
    }
    __syncthreads();
    float mu = sh[8];
    float inv = rsqrtf(sh[9] - mu * mu + 1e-5f);
    for (int k = tid; k < H; k += 128)
        rowb[k] = __float2bfloat16(fmaxf((row[k] - mu) * inv * gp[k] + bp[k], 0.f));
}

// ---------------- fixup: head-target + root terms only ----------------
__global__ void fixup_kernel(const int* __restrict__ tgt) {
    int b = blockIdx.x;
    int lane = threadIdx.x;  // 32
    int t  = (lane < LTGT) ? tgt[b * LTGT + lane] : -1;
    int uq = (lane < LTGT) ? g_uniq[b * LTGT + lane] : 0;

    float corr = 0.f;
    if (uq && t >= 0 && t < SHORTN) corr -= g_hl[b * NHEAD + t];
    if (lane < 3) {
        float l = g_hl[b * NHEAD + SHORTN + lane];
        float a = g_active[b * 3 + lane];
        corr += -a * (fmaxf(l, 0.f) + log1pf(__expf(-fabsf(l))));
        g_root[b * 3 + lane] = 1.f / (1.f + __expf(-l));
    }
    #pragma unroll
    for (int o = 16; o; o >>= 1) corr += __shfl_xor_sync(0xffffffffu, corr, o);
    if (lane == 0) atomicAdd(&g_rowAcc[b], corr);
}

// ---------------- fused tail GEMM + BCE + rare-branch y=1 corrections ----------------
__global__ void __launch_bounds__(256) tail_kernel(const float* __restrict__ w2_0,
                                                   const float* __restrict__ w2_1,
                                                   const float* __restrict__ w2_2) {
    __shared__ __align__(16) __nv_bfloat16 smA[128 * 64];
    __shared__ __align__(16) __nv_bfloat16 smB[128 * 64];
    __shared__ int s_cnt;

    int bx = blockIdx.x;
    const float* W2; int hoff, K, osz, cl, nb;
    if (bx < 79)       { W2 = w2_0; hoff = 0;      K = 384; osz = 10000; cl = 0; nb = bx; }
    else if (bx < 298) { W2 = w2_1; hoff = 98304;  K = 192; osz = 28000; cl = 1; nb = bx - 79; }
    else               { W2 = w2_2; hoff = 147456; K = 96;  osz = 60000; cl = 2; nb = bx - 298; }

    int nloc = nb << 7;
    int nval = osz - nloc; if (nval > 128) nval = 128;
    int bm0 = blockIdx.y * 128;
    int myblk = blockIdx.y * 767 + bx;

    float c[2][8][4] = {};
    mma_loop(g_hb + hoff, K, bm0, W2, nloc, nval, K, smA, smB, c);

    int tid = threadIdx.x;
    int lane = tid & 31, wid = tid >> 5;
    int wm = wid & 3, wn = wid >> 2;
    float* sRow = reinterpret_cast<float*>(smA);
    int*   sList = reinterpret_cast<int*>(smB);
    if (tid < 128) sRow[tid] = 0.f;
    if (tid == 0) s_cnt = 0;
    __syncthreads();

    // gather this block's y==1 targets
    for (int i = tid; i < MROWS * LTGT; i += 256) {
        int pk = g_tpack[i];
        if ((pk >> 14) == myblk) sList[atomicAdd(&s_cnt, 1)] = pk & 0x3FFF;
    }
    __syncthreads();

    // per-thread 64-bit slot mask (slot = tt<<5 | n<<2 | q<<1 | r8)
    uint64_t mask = 0;
    int cnt = s_cnt;
    for (int i = 0; i < cnt; ++i) {
        int val = sList[i];
        int row = (val >> 7) & 127, col = val & 127;
        int wo = ((col >> 6) << 2) | (row >> 5);
        int lo = ((row & 7) << 2) | ((col >> 1) & 3);
        if (wid == wo && lane == lo) {
            int slot = (((row >> 4) & 1) << 5) | (((col >> 3) & 7) << 2)
                     | ((col & 1) << 1) | ((row >> 3) & 1);
            mask |= 1ull << slot;
        }
    }

    // ---- unconditional y0 epilogue (identical structure to the 100.8us run) ----
    #pragma unroll
    for (int tt = 0; tt < 2; ++tt) {
        int lr = wm * 32 + tt * 16 + (lane >> 2);
        float root0 = g_root[(bm0 + lr) * 3 + cl];
        float root1 = g_root[(bm0 + lr + 8) * 3 + cl];
        float rs0 = 0.f, rs1 = 0.f;
        float pn0 = 1.f, pd0 = 1.f, pn1 = 1.f, pd1 = 1.f;
        #pragma unroll
        for (int n = 0; n < 8; ++n) {
            int col = wn * 64 + n * 8 + (lane & 3) * 2;
            #pragma unroll
            for (int q = 0; q < 2; ++q) {
                if (col + q < nval) {
                    float e0 = __expf(-c[tt][n][q]);
                    float e1 = __expf(-c[tt][n][2 + q]);
                    pn0 *= (1.f + e0 - root0); pd0 *= (1.f + e0);
                    pn1 *= (1.f + e1 - root1); pd1 *= (1.f + e1);
                }
            }
            if (n & 1) {
                rs0 += __logf(pd0) - __logf(pn0);
                rs1 += __logf(pd1) - __logf(pn1);
                pn0 = pd0 = pn1 = pd1 = 1.f;
            }
        }
        atomicAdd(&sRow[lr], rs0);
        atomicAdd(&sRow[lr + 8], rs1);
    }

    // ---- rare-branch y==1 corrections (static indices, taken by <=3 threads/block) ----
    if (mask != 0) {
        #pragma unroll
        for (int tt = 0; tt < 2; ++tt) {
            #pragma unroll
            for (int r8 = 0; r8 < 2; ++r8) {
                #pragma unroll
                for (int n = 0; n < 8; ++n) {
                    #pragma unroll
                    for (int q = 0; q < 2; ++q) {
                        const int slot = (tt << 5) | (n << 2) | (q << 1) | r8;
                        if (mask & (1ull << slot)) {
                            int lr = wm * 32 + tt * 16 + r8 * 8 + (lane >> 2);
                            float root = g_root[(bm0 + lr) * 3 + cl];
                            float l = c[tt][n][r8 * 2 + q];
                            float e = __expf(-l);
                            float tq = 1.f + e;
                            // replace y0 = log(tq) - log(tq-root) with y1 = -max(log(root/tq), -100)
                            float corr = -fmaxf(__logf(root) - __logf(tq), -100.f)
                                         - __logf(tq) + __logf(tq - root);
                            atomicAdd(&sRow[lr], corr);
                        }
                    }
                }
            }
        }
    }
    __syncthreads();

    if (tid < 128) {
        float act = g_active[(bm0 + tid) * 3 + cl];
        if (act != 0.f) atomicAdd(&g_rowAcc[bm0 + tid], act * sRow[tid]);
    }
}

// ---------------- finalize ----------------
__global__ void finalize_kernel(float* __restrict__ out) {
    int tid = threadIdx.x;   // 256
    float v = g_rowAcc[tid] / g_num[tid];
    #pragma unroll
    for (int o = 16; o; o >>= 1) v += __shfl_xor_sync(0xffffffffu, v, o);
    __shared__ float sh[8];
    if ((tid & 31) == 0) sh[tid >> 5] = v;
    __syncthreads();
    if (tid == 0) {
        float s = 0.f;
        #pragma unroll
        for (int i = 0; i < 8; ++i) s += sh[i];
        out[0] = s / 256.f;
    }
}

// ---------------- launch ----------------
extern "C" void kernel_launch(void* const* d_in, const int* in_sizes, int n_in,
                              void* d_out, int out_size) {
    const float* x = nullptr;
    const float* headW = nullptr;
    const int* tgt = nullptr;
    const float* w1[3] = {nullptr, nullptr, nullptr};
    const float* w2[3] = {nullptr, nullptr, nullptr};
    const float* gb_a[3] = {nullptr, nullptr, nullptr};
    const float* gb_b[3] = {nullptr, nullptr, nullptr};
    int gbcount[3] = {0, 0, 0};

    for (int i = 0; i < n_in; ++i) {
        int s = in_sizes[i];
        const float* p = (const float*)d_in[i];
        switch (s) {
            case 196608:  x = p; break;
            case 1538304: headW = p; break;
            case 5120:    tgt = (const int*)d_in[i]; break;
            case 294912:  w1[0] = p; break;
            case 147456:  w1[1] = p; break;
            case 73728:   w1[2] = p; break;
            case 3840000: w2[0] = p; break;
            case 5376000: w2[1] = p; break;
            case 5760000: w2[2] = p; break;
            case 384: if (gbcount[0]++ == 0) gb_a[0] = p; else gb_b[0] = p; break;
            case 192: if (gbcount[1]++ == 0) gb_a[1] = p; else gb_b[1] = p; break;
            case 96:  if (gbcount[2]++ == 0) gb_a[2] = p; else gb_b[2] = p; break;
            default: break;
        }
    }

    prep_kernel<<<MROWS, 256>>>(x, tgt);
    mm1_kernel<<<dim3(22, 2), 256>>>(headW, w1[0], w1[1], w1[2]);
    ln_kernel<<<dim3(MROWS, 3), 128>>>(gb_a[0], gb_b[0], gb_a[1], gb_b[1], gb_a[2], gb_b[2]);
    fixup_kernel<<<MROWS, 32>>>(tgt);
    tail_kernel<<<dim3(767, 2), 256>>>(w2[0], w2[1], w2[2]);
    finalize_kernel<<<1, 256>>>((float*)d_out);
}

// round 10
// speedup vs baseline: 1.2195x; 1.2195x over previous
#include <cuda_runtime.h>
#include <cuda_bf16.h>
#include <math.h>
#include <stdint.h>

#define MROWS  256
#define INF_   768
#define SHORTN 2000
#define NHEAD  2003
#define LTGT   20

// clusters: lows 2000,12000,40000,100000; OSZ 10000,28000,60000; HSZ 384,192,96

// ---------------- device scratch ----------------
__device__ __align__(16) __nv_bfloat16 g_xb[MROWS * INF_];
__device__ __align__(16) float          g_h[MROWS * 672];
__device__ __align__(16) __nv_bfloat16 g_hb[MROWS * 672];
__device__ __align__(16) float          g_hl[MROWS * NHEAD];
__device__ float g_rowAcc[MROWS];
__device__ float g_num[MROWS];
__device__ float g_active[MROWS * 3];
__device__ float g_root[MROWS * 3];
__device__ int   g_uniq[MROWS * LTGT];

__device__ __forceinline__ uint32_t smem_u32(const void* p) {
    uint32_t a;
    asm("{ .reg .u64 t; cvta.to.shared.u64 t, %1; cvt.u32.u64 %0, t; }" : "=r"(a) : "l"(p));
    return a;
}

#define LDSM_X4(d0, d1, d2, d3, addr) \
    asm volatile("ldmatrix.sync.aligned.m8n8.x4.shared.b16 {%0,%1,%2,%3}, [%4];" \
        : "=r"(d0), "=r"(d1), "=r"(d2), "=r"(d3) : "r"(addr))

#define MMA16816(c, a, b) \
    asm volatile("mma.sync.aligned.m16n8k16.row.col.f32.bf16.bf16.f32 " \
        "{%0,%1,%2,%3},{%4,%5,%6,%7},{%8,%9},{%0,%1,%2,%3};" \
        : "+f"((c)[0]), "+f"((c)[1]), "+f"((c)[2]), "+f"((c)[3]) \
        : "r"((a)[0]), "r"((a)[1]), "r"((a)[2]), "r"((a)[3]), "r"((b)[0]), "r"((b)[1]))

// ---------------- warp-MMA mainloop (K-chunk 64, 128B smem rows) ----------------
__device__ __forceinline__ void mma_loop(
    const __nv_bfloat16* __restrict__ A, int ldA, int bm0,
    const float* __restrict__ W, int nloc, int nval, int K,
    __nv_bfloat16* smA, __nv_bfloat16* smB, float c[2][8][4])
{
    int tid = threadIdx.x;
    int lane = tid & 31, wid = tid >> 5;
    int wm = wid & 3, wn = wid >> 2;
    int lo3 = lane & 7, gg1 = (lane >> 3) & 1, gg2 = (lane >> 4) & 1;
    uint32_t smAu = smem_u32(smA), smBu = smem_u32(smB);

    int nchunk = (K + 63) >> 6;
    for (int ch = 0; ch < nchunk; ++ch) {
        int kbase = ch << 6;
        int kreal = K - kbase; if (kreal > 64) kreal = 64;
        __syncthreads();

        #pragma unroll
        for (int it = 0; it < 4; ++it) {
            int idx = tid + it * 256;
            int r = idx >> 3, kc = idx & 7;
            if (kc * 8 < kreal) {
                uint4 v = *reinterpret_cast<const uint4*>(
                    A + (size_t)(bm0 + r) * ldA + kbase + kc * 8);
                *reinterpret_cast<uint4*>(
                    reinterpret_cast<char*>(smA) + r * 128 + ((kc ^ (r & 7)) << 4)) = v;
            }
        }
        #pragma unroll
        for (int it = 0; it < 4; ++it) {
            int idx = tid + it * 256;
            int r = idx >> 3, kc = idx & 7;
            if (kc * 8 < kreal) {
                uint4 o = make_uint4(0u, 0u, 0u, 0u);
                if (r < nval) {
                    const float* s = W + (size_t)(nloc + r) * K + kbase + kc * 8;
                    float4 v0 = *reinterpret_cast<const float4*>(s);
                    float4 v1 = *reinterpret_cast<const float4*>(s + 4);
                    asm("cvt.rn.bf16x2.f32 %0, %1, %2;" : "=r"(o.x) : "f"(v0.y), "f"(v0.x));
                    asm("cvt.rn.bf16x2.f32 %0, %1, %2;" : "=r"(o.y) : "f"(v0.w), "f"(v0.z));
                    asm("cvt.rn.bf16x2.f32 %0, %1, %2;" : "=r"(o.z) : "f"(v1.y), "f"(v1.x));
                    asm("cvt.rn.bf16x2.f32 %0, %1, %2;" : "=r"(o.w) : "f"(v1.w), "f"(v1.z));
                }
                *reinterpret_cast<uint4*>(
                    reinterpret_cast<char*>(smB) + r * 128 + ((kc ^ (r & 7)) << 4)) = o;
            }
        }
        __syncthreads();

        int ks = kreal >> 4;
        for (int s = 0; s < ks; ++s) {
            uint32_t a[2][4];
            #pragma unroll
            for (int t = 0; t < 2; ++t) {
                int row = wm * 32 + t * 16 + gg1 * 8 + lo3;
                uint32_t ad = smAu + row * 128 + (((2 * s + gg2) ^ (row & 7)) << 4);
                LDSM_X4(a[t][0], a[t][1], a[t][2], a[t][3], ad);
            }
            uint32_t b[8][2];
            #pragma unroll
            for (int p = 0; p < 4; ++p) {
                int row = wn * 64 + p * 16 + gg2 * 8 + lo3;
                uint32_t bd = smBu + row * 128 + (((2 * s + gg1) ^ (row & 7)) << 4);
                LDSM_X4(b[2 * p][0], b[2 * p][1], b[2 * p + 1][0], b[2 * p + 1][1], bd);
            }
            #pragma unroll
            for (int t = 0; t < 2; ++t)
                #pragma unroll
                for (int n = 0; n < 8; ++n)
                    MMA16816(c[t][n], a[t], b[n]);
        }
    }
    __syncthreads();
}

// ---------------- prep: x -> bf16, per-row init ----------------
__global__ void prep_kernel(const float* __restrict__ x, const int* __restrict__ tgt) {
    int b = blockIdx.x;
    int tid = threadIdx.x;
    for (int k = tid; k < INF_; k += 256)
        g_xb[b * INF_ + k] = __float2bfloat16(x[(size_t)b * INF_ + k]);

    if (tid < 32) {
        int lane = tid;
        int t = (lane < LTGT) ? tgt[b * LTGT + lane] : -1;
        int uniq = (lane < LTGT) ? 1 : 0;
        #pragma unroll
        for (int j = 0; j < LTGT; ++j) {
            int tj = __shfl_sync(0xffffffffu, t, j);
            if (j < lane && tj == t) uniq = 0;
        }
        if (lane < LTGT) g_uniq[b * LTGT + lane] = uniq;

        const int lows[4] = {2000, 12000, 40000, 100000};
        float num = (float)SHORTN;
        #pragma unroll
        for (int i = 0; i < 3; ++i) {
            bool in = (lane < LTGT) && (t >= lows[i]) && (t < lows[i + 1]);
            unsigned ball = __ballot_sync(0xffffffffu, in);
            float a = ball ? 1.f : 0.f;
            if (lane == 0) g_active[b * 3 + i] = a;
            num += (1.f - a) + a * (float)(lows[i + 1] - lows[i]);
        }
        if (lane == 0) { g_num[b] = num; g_rowAcc[b] = 0.f; }
    }
}

// ---------------- mm1: head + hidden GEMMs (128x128) ----------------
__global__ void __launch_bounds__(256) mm1_kernel(const float* __restrict__ headW,
                                                  const float* __restrict__ w1_0,
                                                  const float* __restrict__ w1_1,
                                                  const float* __restrict__ w1_2) {
    __shared__ __align__(16) __nv_bfloat16 smA[128 * 64];
    __shared__ __align__(16) __nv_bfloat16 smB[128 * 64];

    int t = blockIdx.x;
    int bm0 = blockIdx.y * 128;
    const float* W; float* outF; int ldc, nloc, nval, mode;
    if (t < 16)      { W = headW; outF = g_hl;         ldc = NHEAD; nloc = t << 7;        nval = NHEAD - nloc; if (nval > 128) nval = 128; mode = 1; }
    else if (t < 19) { W = w1_0;  outF = g_h;          ldc = 384;   nloc = (t - 16) << 7; nval = 128; mode = 0; }
    else if (t < 21) { W = w1_1;  outF = g_h + 98304;  ldc = 192;   nloc = (t - 19) << 7; nval = 192 - nloc; if (nval > 128) nval = 128; mode = 0; }
    else             { W = w1_2;  outF = g_h + 147456; ldc = 96;    nloc = 0;             nval = 96;  mode = 0; }

    float c[2][8][4] = {};
    mma_loop(g_xb, INF_, bm0, W, nloc, nval, INF_, smA, smB, c);

    int tid = threadIdx.x;
    int lane = tid & 31, wid = tid >> 5;
    int wm = wid & 3, wn = wid >> 2;
    float* sRow = reinterpret_cast<float*>(smA);
    if (mode == 1) { if (tid < 128) sRow[tid] = 0.f; }
    __syncthreads();

    float rs[2][2] = {{0.f, 0.f}, {0.f, 0.f}};
    #pragma unroll
    for (int tt = 0; tt < 2; ++tt) {
        int r0 = bm0 + wm * 32 + tt * 16 + (lane >> 2);
        #pragma unroll
        for (int n = 0; n < 8; ++n) {
            int col = wn * 64 + n * 8 + (lane & 3) * 2;
            #pragma unroll
            for (int q = 0; q < 2; ++q) {
                if (col + q < nval) {
                    float l0 = c[tt][n][q];
                    float l1 = c[tt][n][2 + q];
                    outF[(size_t)r0 * ldc + nloc + col + q] = l0;
                    outF[(size_t)(r0 + 8) * ldc + nloc + col + q] = l1;
                    if (mode == 1) {
                        rs[tt][0] += fmaxf(l0, 0.f) + log1pf(__expf(-fabsf(l0)));
                        rs[tt][1] += fmaxf(l1, 0.f) + log1pf(__expf(-fabsf(l1)));
                    }
                }
            }
        }
    }
    if (mode == 1) {
        #pragma unroll
        for (int tt = 0; tt < 2; ++tt) {
            int lr = wm * 32 + tt * 16 + (lane >> 2);
            atomicAdd(&sRow[lr], rs[tt][0]);
            atomicAdd(&sRow[lr + 8], rs[tt][1]);
        }
        __syncthreads();
        if (tid < 128) atomicAdd(&g_rowAcc[bm0 + tid], sRow[tid]);
    }
}

// ---------------- LayerNorm + ReLU (fp32 + bf16 out) ----------------
__global__ void ln_kernel(const float* __restrict__ p1a, const float* __restrict__ p2a,
                          const float* __restrict__ p1b, const float* __restrict__ p2b,
                          const float* __restrict__ p1c, const float* __restrict__ p2c) {
    int ci = blockIdx.y;
    int b = blockIdx.x;
    int H, hoff; const float* p1; const float* p2;
    if (ci == 0)      { H = 384; hoff = 0;      p1 = p1a; p2 = p2a; }
    else if (ci == 1) { H = 192; hoff = 98304;  p1 = p1b; p2 = p2b; }
    else              { H = 96;  hoff = 147456; p1 = p1c; p2 = p2c; }
    float* row = g_h + hoff + (size_t)b * H;
    __nv_bfloat16* rowb = g_hb + hoff + (size_t)b * H;

    float v1 = p1[0], v2 = p2[0];
    const float* gp = (fabsf(v1 - 1.f) <= fabsf(v2 - 1.f)) ? p1 : p2;
    const float* bp = (gp == p1) ? p2 : p1;

    int tid = threadIdx.x;   // 128
    float s = 0.f, ss = 0.f;
    for (int k = tid; k < H; k += 128) {
        float v = row[k];
        s += v; ss += v * v;
    }
    #pragma unroll
    for (int o = 16; o; o >>= 1) {
        s  += __shfl_xor_sync(0xffffffffu, s, o);
        ss += __shfl_xor_sync(0xffffffffu, ss, o);
    }
    __shared__ float sh[10];
    int w = tid >> 5;
    if ((tid & 31) == 0) { sh[w] = s; sh[4 + w] = ss; }
    __syncthreads();
    if (tid == 0) {
        float S = sh[0] + sh[1] + sh[2] + sh[3];
        float SS = sh[4] + sh[5] + sh[6] + sh[7];
        sh[8] = S / (float)H;
        sh[9] = SS / (float)H;
    }
    __syncthreads();
    float mu = sh[8];
    float inv = rsqrtf(sh[9] - mu * mu + 1e-5f);
    for (int k = tid; k < H; k += 128) {
        float v = fmaxf((row[k] - mu) * inv * gp[k] + bp[k], 0.f);
        row[k] = v;
        rowb[k] = __float2bfloat16(v);
    }
}

// ---------------- fixup: head-target + root terms (one warp per row) ----------------
__global__ void fixup_kernel(const int* __restrict__ tgt) {
    int b = blockIdx.x;
    int lane = threadIdx.x;  // 32
    int t  = (lane < LTGT) ? tgt[b * LTGT + lane] : -1;
    int uq = (lane < LTGT) ? g_uniq[b * LTGT + lane] : 0;

    float corr = 0.f;
    if (uq && t >= 0 && t < SHORTN) corr -= g_hl[b * NHEAD + t];
    if (lane < 3) {
        float l = g_hl[b * NHEAD + SHORTN + lane];
        float a = g_active[b * 3 + lane];
        corr += -a * (fmaxf(l, 0.f) + log1pf(__expf(-fabsf(l))));
        g_root[b * 3 + lane] = 1.f / (1.f + __expf(-l));
    }
    #pragma unroll
    for (int o = 16; o; o >>= 1) corr += __shfl_xor_sync(0xffffffffu, corr, o);
    if (lane == 0) atomicAdd(&g_rowAcc[b], corr);
}

// ---------------- fixup2: y=1 tail dot products, one block per (row, slot) ----------------
__global__ void fixup2_kernel(const int* __restrict__ tgt,
                              const float* __restrict__ w2_0,
                              const float* __restrict__ w2_1,
                              const float* __restrict__ w2_2) {
    int b = blockIdx.x;
    int j = blockIdx.y;
    int lane = threadIdx.x;  // 32

    int t = tgt[b * LTGT + j];
    if (t < SHORTN || !g_uniq[b * LTGT + j]) return;

    const float* w2; int H, hoff, low, ci;
    if (t < 12000)      { w2 = w2_0; H = 384; hoff = 0;      low = 2000;  ci = 0; }
    else if (t < 40000) { w2 = w2_1; H = 192; hoff = 98304;  low = 12000; ci = 1; }
    else                { w2 = w2_2; H = 96;  hoff = 147456; low = 40000; ci = 2; }
    int col = t - low;
    const float* hrow = g_h + hoff + (size_t)b * H;
    const float* wrow = w2 + (size_t)col * H;
    float part = 0.f;
    for (int k = lane; k < H; k += 32) part += hrow[k] * wrow[k];
    #pragma unroll
    for (int o = 16; o; o >>= 1) part += __shfl_xor_sync(0xffffffffu, part, o);
    if (lane == 0) {
        float r = g_root[b * 3 + ci];
        float s = 1.f / (1.f + __expf(-part));
        float p = r * s;
        float tc = -fmaxf(logf(p), -100.f) + fmaxf(log1pf(-p), -100.f);
        atomicAdd(&g_rowAcc[b], tc);
    }
}

// ---------------- fused tail GEMM + BCE (exact 100.8us structure) ----------------
__global__ void __launch_bounds__(256) tail_kernel(const float* __restrict__ w2_0,
                                                   const float* __restrict__ w2_1,
                                                   const float* __restrict__ w2_2) {
    __shared__ __align__(16) __nv_bfloat16 smA[128 * 64];
    __shared__ __align__(16) __nv_bfloat16 smB[128 * 64];

    int bx = blockIdx.x;
    const float* W2; int hoff, K, osz, cl, nb;
    if (bx < 79)       { W2 = w2_0; hoff = 0;      K = 384; osz = 10000; cl = 0; nb = bx; }
    else if (bx < 298) { W2 = w2_1; hoff = 98304;  K = 192; osz = 28000; cl = 1; nb = bx - 79; }
    else               { W2 = w2_2; hoff = 147456; K = 96;  osz = 60000; cl = 2; nb = bx - 298; }

    int nloc = nb << 7;
    int nval = osz - nloc; if (nval > 128) nval = 128;
    int bm0 = blockIdx.y * 128;

    float c[2][8][4] = {};
    mma_loop(g_hb + hoff, K, bm0, W2, nloc, nval, K, smA, smB, c);

    int tid = threadIdx.x;
    int lane = tid & 31, wid = tid >> 5;
    int wm = wid & 3, wn = wid >> 2;
    float* sRow = reinterpret_cast<float*>(smA);
    if (tid < 128) sRow[tid] = 0.f;
    __syncthreads();

    #pragma unroll
    for (int tt = 0; tt < 2; ++tt) {
        int lr = wm * 32 + tt * 16 + (lane >> 2);
        float root0 = g_root[(bm0 + lr) * 3 + cl];
        float root1 = g_root[(bm0 + lr + 8) * 3 + cl];
        float rs0 = 0.f, rs1 = 0.f;
        float pn0 = 1.f, pd0 = 1.f, pn1 = 1.f, pd1 = 1.f;
        #pragma unroll
        for (int n = 0; n < 8; ++n) {
            int col = wn * 64 + n * 8 + (lane & 3) * 2;
            #pragma unroll
            for (int q = 0; q < 2; ++q) {
                if (col + q < nval) {
                    float e0 = __expf(-c[tt][n][q]);
                    float e1 = __expf(-c[tt][n][2 + q]);
                    pn0 *= (1.f + e0 - root0); pd0 *= (1.f + e0);
                    pn1 *= (1.f + e1 - root1); pd1 *= (1.f + e1);
                }
            }
            if (n & 1) {   // flush every 4 elements/row
                rs0 += __logf(pd0) - __logf(pn0);
                rs1 += __logf(pd1) - __logf(pn1);
                pn0 = pd0 = pn1 = pd1 = 1.f;
            }
        }
        atomicAdd(&sRow[lr], rs0);
        atomicAdd(&sRow[lr + 8], rs1);
    }
    __syncthreads();
    if (tid < 128) {
        float act = g_active[(bm0 + tid) * 3 + cl];
        if (act != 0.f) atomicAdd(&g_rowAcc[bm0 + tid], act * sRow[tid]);
    }
}

// ---------------- finalize ----------------
__global__ void finalize_kernel(float* __restrict__ out) {
    int tid = threadIdx.x;   // 256
    float v = g_rowAcc[tid] / g_num[tid];
    #pragma unroll
    for (int o = 16; o; o >>= 1) v += __shfl_xor_sync(0xffffffffu, v, o);
    __shared__ float sh[8];
    if ((tid & 31) == 0) sh[tid >> 5] = v;
    __syncthreads();
    if (tid == 0) {
        float s = 0.f;
        #pragma unroll
        for (int i = 0; i < 8; ++i) s += sh[i];
        out[0] = s / 256.f;
    }
}

// ---------------- launch ----------------
extern "C" void kernel_launch(void* const* d_in, const int* in_sizes, int n_in,
                              void* d_out, int out_size) {
    const float* x = nullptr;
    const float* headW = nullptr;
    const int* tgt = nullptr;
    const float* w1[3] = {nullptr, nullptr, nullptr};
    const float* w2[3] = {nullptr, nullptr, nullptr};
    const float* gb_a[3] = {nullptr, nullptr, nullptr};
    const float* gb_b[3] = {nullptr, nullptr, nullptr};
    int gbcount[3] = {0, 0, 0};

    for (int i = 0; i < n_in; ++i) {
        int s = in_sizes[i];
        const float* p = (const float*)d_in[i];
        switch (s) {
            case 196608:  x = p; break;
            case 1538304: headW = p; break;
            case 5120:    tgt = (const int*)d_in[i]; break;
            case 294912:  w1[0] = p; break;
            case 147456:  w1[1] = p; break;
            case 73728:   w1[2] = p; break;
            case 3840000: w2[0] = p; break;
            case 5376000: w2[1] = p; break;
            case 5760000: w2[2] = p; break;
            case 384: if (gbcount[0]++ == 0) gb_a[0] = p; else gb_b[0] = p; break;
            case 192: if (gbcount[1]++ == 0) gb_a[1] = p; else gb_b[1] = p; break;
            case 96:  if (gbcount[2]++ == 0) gb_a[2] = p; else gb_b[2] = p; break;
            default: break;
        }
    }

    prep_kernel<<<MROWS, 256>>>(x, tgt);
    mm1_kernel<<<dim3(22, 2), 256>>>(headW, w1[0], w1[1], w1[2]);
    ln_kernel<<<dim3(MROWS, 3), 128>>>(gb_a[0], gb_b[0], gb_a[1], gb_b[1], gb_a[2], gb_b[2]);
    fixup_kernel<<<MROWS, 32>>>(tgt);
    fixup2_kernel<<<dim3(MROWS, LTGT), 32>>>(tgt, w2[0], w2[1], w2[2]);
    tail_kernel<<<dim3(767, 2), 256>>>(w2[0], w2[1], w2[2]);
    finalize_kernel<<<1, 256>>>((float*)d_out);
}